// round 1
// baseline (speedup 1.0000x reference)
#include <cuda_runtime.h>
#include <cstddef>

#define NMAX 100000
#define D 128

// Scratch (device-global, allocation-free per harness rules)
__device__ float g_agg[(size_t)NMAX * D];
__device__ float g_cnt[NMAX];
__device__ float g_h1[(size_t)NMAX * D];
__device__ float g_h2[(size_t)NMAX * D];

// ---------------------------------------------------------------------------
// Zero agg + cnt
// ---------------------------------------------------------------------------
__global__ void zero_kernel(int n_agg4, int n_cnt) {
    float4* a4 = reinterpret_cast<float4*>(g_agg);
    int i = blockIdx.x * blockDim.x + threadIdx.x;
    int stride = gridDim.x * blockDim.x;
    float4 z = make_float4(0.f, 0.f, 0.f, 0.f);
    for (int j = i; j < n_agg4; j += stride) a4[j] = z;
    for (int j = i; j < n_cnt; j += stride) g_cnt[j] = 0.f;
}

// ---------------------------------------------------------------------------
// Edge scatter: one warp per edge. lane handles 4 consecutive floats.
// agg[dst] += feat[src]; cnt[dst] += 1
// ---------------------------------------------------------------------------
__global__ void __launch_bounds__(256) scatter_kernel(
    const float* __restrict__ feat, const int* __restrict__ ei, int E)
{
    int warp = (blockIdx.x * 256 + threadIdx.x) >> 5;
    int lane = threadIdx.x & 31;
    if (warp >= E) return;
    int s = __ldg(ei + warp);        // src
    int d = __ldg(ei + E + warp);    // dst
    float4 v = __ldg(reinterpret_cast<const float4*>(feat) + (size_t)s * 32 + lane);
    float* o = g_agg + (size_t)d * D + lane * 4;
    atomicAdd(o + 0, v.x);
    atomicAdd(o + 1, v.y);
    atomicAdd(o + 2, v.z);
    atomicAdd(o + 3, v.w);
    if (lane == 0) atomicAdd(g_cnt + d, 1.0f);
}

// ---------------------------------------------------------------------------
// Fused SAGE layer: out = relu((agg/max(cnt,1)) @ wl + xin @ wr + bias)
// Block: 256 threads, tile 64 rows x 128 cols. Weights (2x 64KB) in smem.
// Thread (lane, wy): cols lane*4..lane*4+3, rows wy*8+i (i=0..7).
// Per-warp row loads are uniform -> smem broadcast, conflict-free.
// ---------------------------------------------------------------------------
__global__ void __launch_bounds__(256) layer_kernel(
    const float* __restrict__ xin,
    const float* __restrict__ wl, const float* __restrict__ wr,
    const float* __restrict__ bias, float* __restrict__ out, int n)
{
    extern __shared__ float smem[];
    float4* s_wl4 = reinterpret_cast<float4*>(smem);            // 128x128
    float4* s_wr4 = reinterpret_cast<float4*>(smem + 16384);    // 128x128
    float4* s_a4  = reinterpret_cast<float4*>(smem + 32768);    // 64x128
    float4* s_x4  = reinterpret_cast<float4*>(smem + 40960);    // 64x128

    int tid = threadIdx.x;

    const float4* wl4 = reinterpret_cast<const float4*>(wl);
    const float4* wr4 = reinterpret_cast<const float4*>(wr);
#pragma unroll
    for (int i = 0; i < 16; i++) {
        s_wl4[tid + i * 256] = __ldg(wl4 + tid + i * 256);
        s_wr4[tid + i * 256] = __ldg(wr4 + tid + i * 256);
    }

    int r0 = blockIdx.x * 64;
    const float4* agg4 = reinterpret_cast<const float4*>(g_agg);
    const float4* x4   = reinterpret_cast<const float4*>(xin);
#pragma unroll
    for (int i = 0; i < 8; i++) {
        int f   = tid + i * 256;   // 0..2047 over 64 rows * 32 float4
        int row = f >> 5;
        int c4  = f & 31;
        int gr  = r0 + row;
        if (gr >= n) gr = n - 1;   // clamp (stores are guarded later)
        float inv = 1.0f / fmaxf(g_cnt[gr], 1.0f);
        float4 av = agg4[(size_t)gr * 32 + c4];
        av.x *= inv; av.y *= inv; av.z *= inv; av.w *= inv;
        s_a4[f] = av;
        s_x4[f] = x4[(size_t)gr * 32 + c4];
    }
    __syncthreads();

    int lane = tid & 31;   // output col group
    int wy   = tid >> 5;   // 0..7

    float acc[8][4];
#pragma unroll
    for (int i = 0; i < 8; i++)
#pragma unroll
        for (int c = 0; c < 4; c++) acc[i][c] = 0.f;

#pragma unroll 2
    for (int k4 = 0; k4 < 32; k4++) {
        float4 wlv[4], wrv[4];
#pragma unroll
        for (int dk = 0; dk < 4; dk++) {
            wlv[dk] = s_wl4[(k4 * 4 + dk) * 32 + lane];
            wrv[dk] = s_wr4[(k4 * 4 + dk) * 32 + lane];
        }
#pragma unroll
        for (int i = 0; i < 8; i++) {
            int row = wy * 8 + i;
            float4 a  = s_a4[row * 32 + k4];
            float4 xv = s_x4[row * 32 + k4];
            acc[i][0] += a.x * wlv[0].x + a.y * wlv[1].x + a.z * wlv[2].x + a.w * wlv[3].x
                       + xv.x * wrv[0].x + xv.y * wrv[1].x + xv.z * wrv[2].x + xv.w * wrv[3].x;
            acc[i][1] += a.x * wlv[0].y + a.y * wlv[1].y + a.z * wlv[2].y + a.w * wlv[3].y
                       + xv.x * wrv[0].y + xv.y * wrv[1].y + xv.z * wrv[2].y + xv.w * wrv[3].y;
            acc[i][2] += a.x * wlv[0].z + a.y * wlv[1].z + a.z * wlv[2].z + a.w * wlv[3].z
                       + xv.x * wrv[0].z + xv.y * wrv[1].z + xv.z * wrv[2].z + xv.w * wrv[3].z;
            acc[i][3] += a.x * wlv[0].w + a.y * wlv[1].w + a.z * wlv[2].w + a.w * wlv[3].w
                       + xv.x * wrv[0].w + xv.y * wrv[1].w + xv.z * wrv[2].w + xv.w * wrv[3].w;
        }
    }

    float4 bv = __ldg(reinterpret_cast<const float4*>(bias) + lane);
#pragma unroll
    for (int i = 0; i < 8; i++) {
        int gr = r0 + wy * 8 + i;
        if (gr < n) {
            float4 o;
            o.x = fmaxf(acc[i][0] + bv.x, 0.f);
            o.y = fmaxf(acc[i][1] + bv.y, 0.f);
            o.z = fmaxf(acc[i][2] + bv.z, 0.f);
            o.w = fmaxf(acc[i][3] + bv.w, 0.f);
            reinterpret_cast<float4*>(out)[(size_t)gr * 32 + lane] = o;
        }
    }
}

// ---------------------------------------------------------------------------
// Output head: out[row] = [h1[row], h2[row]] @ w_out + b_out   (K=256, N=40)
// One warp per row; lane -> col lane, and col 32+lane for lane<8.
// ---------------------------------------------------------------------------
__global__ void __launch_bounds__(256) out_kernel(
    const float* __restrict__ w_out, const float* __restrict__ b_out,
    float* __restrict__ out, int n)
{
    __shared__ float ws[256 * 40];
    int tid = threadIdx.x;
#pragma unroll
    for (int i = 0; i < 40; i++) ws[tid + i * 256] = __ldg(w_out + tid + i * 256);
    __syncthreads();

    int warp = tid >> 5, lane = tid & 31;
    int row = blockIdx.x * 8 + warp;
    if (row >= n) return;

    const float* hr1 = g_h1 + (size_t)row * D;
    const float* hr2 = g_h2 + (size_t)row * D;

    float acc_a0 = 0.f, acc_a1 = 0.f;   // col = lane (two chains for ILP)
    float acc_b0 = 0.f, acc_b1 = 0.f;   // col = 32+lane (lane < 8)
    bool hi = (lane < 8);

#pragma unroll 8
    for (int k = 0; k < 128; k += 2) {
        float h0 = __ldg(hr1 + k), h1v = __ldg(hr1 + k + 1);
        acc_a0 += h0 * ws[k * 40 + lane];
        acc_a1 += h1v * ws[(k + 1) * 40 + lane];
        if (hi) {
            acc_b0 += h0 * ws[k * 40 + 32 + lane];
            acc_b1 += h1v * ws[(k + 1) * 40 + 32 + lane];
        }
    }
#pragma unroll 8
    for (int k = 0; k < 128; k += 2) {
        float h0 = __ldg(hr2 + k), h1v = __ldg(hr2 + k + 1);
        acc_a0 += h0 * ws[(128 + k) * 40 + lane];
        acc_a1 += h1v * ws[(129 + k) * 40 + lane];
        if (hi) {
            acc_b0 += h0 * ws[(128 + k) * 40 + 32 + lane];
            acc_b1 += h1v * ws[(129 + k) * 40 + 32 + lane];
        }
    }

    out[(size_t)row * 40 + lane] = acc_a0 + acc_a1 + __ldg(b_out + lane);
    if (hi) out[(size_t)row * 40 + 32 + lane] = acc_b0 + acc_b1 + __ldg(b_out + 32 + lane);
}

// ---------------------------------------------------------------------------
extern "C" void kernel_launch(void* const* d_in, const int* in_sizes, int n_in,
                              void* d_out, int out_size)
{
    const float* x     = (const float*)d_in[0];
    const int*   ei1   = (const int*)d_in[1];
    const int*   ei2   = (const int*)d_in[2];
    const float* wl1   = (const float*)d_in[3];
    const float* wr1   = (const float*)d_in[4];
    const float* b1    = (const float*)d_in[5];
    const float* wl2   = (const float*)d_in[6];
    const float* wr2   = (const float*)d_in[7];
    const float* b2    = (const float*)d_in[8];
    const float* w_out = (const float*)d_in[9];
    const float* b_out = (const float*)d_in[10];

    int n  = in_sizes[0] / D;
    int E1 = in_sizes[1] / 2;
    int E2 = in_sizes[2] / 2;
    int n_rows_out = out_size / 40;   // == batch_size (== n in this dataset)

    void *p_h1 = nullptr, *p_h2 = nullptr;
    cudaGetSymbolAddress(&p_h1, g_h1);
    cudaGetSymbolAddress(&p_h2, g_h2);
    float* h1 = (float*)p_h1;
    float* h2 = (float*)p_h2;

    cudaFuncSetAttribute(layer_kernel,
                         cudaFuncAttributeMaxDynamicSharedMemorySize, 196608);

    int layer_blocks = (n + 63) / 64;

    // ---- layer 1 ----
    zero_kernel<<<2048, 256>>>(n * 32, n);
    scatter_kernel<<<(E1 * 32 + 255) / 256, 256>>>(x, ei1, E1);
    layer_kernel<<<layer_blocks, 256, 196608>>>(x, wl1, wr1, b1, h1, n);

    // ---- layer 2 ----
    zero_kernel<<<2048, 256>>>(n * 32, n);
    scatter_kernel<<<(E2 * 32 + 255) / 256, 256>>>(h1, ei2, E2);
    layer_kernel<<<layer_blocks, 256, 196608>>>(h1, wl2, wr2, b2, h2, n);

    // ---- JK cat + linear head ----
    out_kernel<<<(n_rows_out + 7) / 8, 256>>>(w_out, b_out, (float*)d_out, n_rows_out);
}

// round 2
// speedup vs baseline: 2.5447x; 2.5447x over previous
#include <cuda_runtime.h>
#include <cstddef>

#define NMAX 100000
#define EMAX 1700000
#define D 128

// Scratch (device-global, allocation-free per harness rules)
__device__ float g_agg[(size_t)NMAX * D];
__device__ float g_h1[(size_t)NMAX * D];
__device__ float g_h2[(size_t)NMAX * D];
__device__ int   g_deg[NMAX];
__device__ int   g_off[NMAX + 1];
__device__ int   g_cursor[NMAX];
__device__ int   g_nbr[EMAX];
__device__ int   g_aux[1024];

// ---------------------------------------------------------------------------
// CSR build: zero degrees
// ---------------------------------------------------------------------------
__global__ void zero_deg_kernel(int n) {
    int i = blockIdx.x * blockDim.x + threadIdx.x;
    int stride = gridDim.x * blockDim.x;
    for (int j = i; j < n; j += stride) g_deg[j] = 0;
}

// Count in-degree per dst
__global__ void __launch_bounds__(256) count_kernel(const int* __restrict__ ei, int E) {
    int e = blockIdx.x * 256 + threadIdx.x;
    if (e >= E) return;
    atomicAdd(&g_deg[__ldg(ei + E + e)], 1);
}

// Exclusive scan, pass 1: per-1024 chunk scan + block totals
__global__ void __launch_bounds__(1024) scan1_kernel(int n) {
    __shared__ int s[1024];
    int t = threadIdx.x;
    int i = blockIdx.x * 1024 + t;
    int v = (i < n) ? g_deg[i] : 0;
    s[t] = v;
    __syncthreads();
#pragma unroll
    for (int d = 1; d < 1024; d <<= 1) {
        int add = (t >= d) ? s[t - d] : 0;
        __syncthreads();
        s[t] += add;
        __syncthreads();
    }
    if (i < n) g_off[i] = s[t] - v;          // exclusive
    if (t == 1023) g_aux[blockIdx.x] = s[1023];
}

// pass 2: scan block totals (single block)
__global__ void __launch_bounds__(1024) scan2_kernel(int nb) {
    __shared__ int s[1024];
    int t = threadIdx.x;
    int v = (t < nb) ? g_aux[t] : 0;
    s[t] = v;
    __syncthreads();
#pragma unroll
    for (int d = 1; d < 1024; d <<= 1) {
        int add = (t >= d) ? s[t - d] : 0;
        __syncthreads();
        s[t] += add;
        __syncthreads();
    }
    if (t < nb) g_aux[t] = s[t] - v;         // exclusive
}

// pass 3: add block offsets, init cursors
__global__ void __launch_bounds__(256) scan3_kernel(int n) {
    int i = blockIdx.x * 256 + threadIdx.x;
    if (i >= n) return;
    int o = g_off[i] + g_aux[i >> 10];
    g_off[i] = o;
    g_cursor[i] = o;
}

// Fill neighbor buckets: g_nbr[off[dst] ...] = src
__global__ void __launch_bounds__(256) fill_kernel(const int* __restrict__ ei, int E) {
    int e = blockIdx.x * 256 + threadIdx.x;
    if (e >= E) return;
    int s = __ldg(ei + e);
    int d = __ldg(ei + E + e);
    int pos = atomicAdd(&g_cursor[d], 1);
    g_nbr[pos] = s;
}

// ---------------------------------------------------------------------------
// Gather-mean: warp per node. lane owns cols lane*4..lane*4+3.
// agg[v] = mean over neighbors of feat[nbr]
// ---------------------------------------------------------------------------
__global__ void __launch_bounds__(256) gather_kernel(const float* __restrict__ feat, int n) {
    int v = (blockIdx.x * 256 + threadIdx.x) >> 5;
    int lane = threadIdx.x & 31;
    if (v >= n) return;
    int start = g_off[v];
    int deg = g_deg[v];
    const float4* f4 = reinterpret_cast<const float4*>(feat);
    float4 acc = make_float4(0.f, 0.f, 0.f, 0.f);
    int i = 0;
    for (; i + 4 <= deg; i += 4) {
        int s0 = __ldg(g_nbr + start + i);
        int s1 = __ldg(g_nbr + start + i + 1);
        int s2 = __ldg(g_nbr + start + i + 2);
        int s3 = __ldg(g_nbr + start + i + 3);
        float4 a = __ldg(f4 + (size_t)s0 * 32 + lane);
        float4 b = __ldg(f4 + (size_t)s1 * 32 + lane);
        float4 c = __ldg(f4 + (size_t)s2 * 32 + lane);
        float4 d = __ldg(f4 + (size_t)s3 * 32 + lane);
        acc.x += (a.x + b.x) + (c.x + d.x);
        acc.y += (a.y + b.y) + (c.y + d.y);
        acc.z += (a.z + b.z) + (c.z + d.z);
        acc.w += (a.w + b.w) + (c.w + d.w);
    }
    for (; i < deg; i++) {
        int s0 = __ldg(g_nbr + start + i);
        float4 a = __ldg(f4 + (size_t)s0 * 32 + lane);
        acc.x += a.x; acc.y += a.y; acc.z += a.z; acc.w += a.w;
    }
    float inv = 1.0f / (float)max(deg, 1);
    acc.x *= inv; acc.y *= inv; acc.z *= inv; acc.w *= inv;
    reinterpret_cast<float4*>(g_agg)[(size_t)v * 32 + lane] = acc;
}

// ---------------------------------------------------------------------------
// Fused SAGE layer: out = relu(agg @ wl + xin @ wr + bias)   (agg pre-divided)
// Block 256, tile 64 rows x 128 cols, both weights in smem.
// ---------------------------------------------------------------------------
__global__ void __launch_bounds__(256) layer_kernel(
    const float* __restrict__ xin,
    const float* __restrict__ wl, const float* __restrict__ wr,
    const float* __restrict__ bias, float* __restrict__ out, int n)
{
    extern __shared__ float smem[];
    float4* s_wl4 = reinterpret_cast<float4*>(smem);            // 128x128
    float4* s_wr4 = reinterpret_cast<float4*>(smem + 16384);    // 128x128
    float4* s_a4  = reinterpret_cast<float4*>(smem + 32768);    // 64x128
    float4* s_x4  = reinterpret_cast<float4*>(smem + 40960);    // 64x128

    int tid = threadIdx.x;

    const float4* wl4 = reinterpret_cast<const float4*>(wl);
    const float4* wr4 = reinterpret_cast<const float4*>(wr);
#pragma unroll
    for (int i = 0; i < 16; i++) {
        s_wl4[tid + i * 256] = __ldg(wl4 + tid + i * 256);
        s_wr4[tid + i * 256] = __ldg(wr4 + tid + i * 256);
    }

    int r0 = blockIdx.x * 64;
    const float4* agg4 = reinterpret_cast<const float4*>(g_agg);
    const float4* x4   = reinterpret_cast<const float4*>(xin);
#pragma unroll
    for (int i = 0; i < 8; i++) {
        int f   = tid + i * 256;   // 0..2047 over 64 rows * 32 float4
        int row = f >> 5;
        int c4  = f & 31;
        int gr  = r0 + row;
        if (gr >= n) gr = n - 1;   // clamp (stores guarded later)
        s_a4[f] = agg4[(size_t)gr * 32 + c4];
        s_x4[f] = x4[(size_t)gr * 32 + c4];
    }
    __syncthreads();

    int lane = tid & 31;   // output col group
    int wy   = tid >> 5;   // 0..7

    float acc[8][4];
#pragma unroll
    for (int i = 0; i < 8; i++)
#pragma unroll
        for (int c = 0; c < 4; c++) acc[i][c] = 0.f;

#pragma unroll 2
    for (int k4 = 0; k4 < 32; k4++) {
        float4 wlv[4], wrv[4];
#pragma unroll
        for (int dk = 0; dk < 4; dk++) {
            wlv[dk] = s_wl4[(k4 * 4 + dk) * 32 + lane];
            wrv[dk] = s_wr4[(k4 * 4 + dk) * 32 + lane];
        }
#pragma unroll
        for (int i = 0; i < 8; i++) {
            int row = wy * 8 + i;
            float4 a  = s_a4[row * 32 + k4];
            float4 xv = s_x4[row * 32 + k4];
            acc[i][0] += a.x * wlv[0].x + a.y * wlv[1].x + a.z * wlv[2].x + a.w * wlv[3].x
                       + xv.x * wrv[0].x + xv.y * wrv[1].x + xv.z * wrv[2].x + xv.w * wrv[3].x;
            acc[i][1] += a.x * wlv[0].y + a.y * wlv[1].y + a.z * wlv[2].y + a.w * wlv[3].y
                       + xv.x * wrv[0].y + xv.y * wrv[1].y + xv.z * wrv[2].y + xv.w * wrv[3].y;
            acc[i][2] += a.x * wlv[0].z + a.y * wlv[1].z + a.z * wlv[2].z + a.w * wlv[3].z
                       + xv.x * wrv[0].z + xv.y * wrv[1].z + xv.z * wrv[2].z + xv.w * wrv[3].z;
            acc[i][3] += a.x * wlv[0].w + a.y * wlv[1].w + a.z * wlv[2].w + a.w * wlv[3].w
                       + xv.x * wrv[0].w + xv.y * wrv[1].w + xv.z * wrv[2].w + xv.w * wrv[3].w;
        }
    }

    float4 bv = __ldg(reinterpret_cast<const float4*>(bias) + lane);
#pragma unroll
    for (int i = 0; i < 8; i++) {
        int gr = r0 + wy * 8 + i;
        if (gr < n) {
            float4 o;
            o.x = fmaxf(acc[i][0] + bv.x, 0.f);
            o.y = fmaxf(acc[i][1] + bv.y, 0.f);
            o.z = fmaxf(acc[i][2] + bv.z, 0.f);
            o.w = fmaxf(acc[i][3] + bv.w, 0.f);
            reinterpret_cast<float4*>(out)[(size_t)gr * 32 + lane] = o;
        }
    }
}

// ---------------------------------------------------------------------------
// Output head: out[row] = [h1[row], h2[row]] @ w_out + b_out   (K=256, Ncls=40)
// Block 256: 128 rows/block. Thread: 4 rows x 5 cols.
// ---------------------------------------------------------------------------
__global__ void __launch_bounds__(256) out_kernel(
    const float* __restrict__ w_out, const float* __restrict__ b_out,
    float* __restrict__ out, int n)
{
    extern __shared__ float sm[];
    float* ws = sm;                 // 256*40 = 10240 floats
    float* hs = sm + 10240;         // 128 rows * 257 floats (padded)

    int tid = threadIdx.x;
    const float4* w4 = reinterpret_cast<const float4*>(w_out);
    float4* ws4 = reinterpret_cast<float4*>(ws);
#pragma unroll
    for (int i = 0; i < 10; i++) ws4[tid + i * 256] = __ldg(w4 + tid + i * 256);

    int r0 = blockIdx.x * 128;
#pragma unroll
    for (int i = 0; i < 32; i++) {
        int f = tid + i * 256;          // 0..8191 = 128 rows * 64 float4
        int row = f >> 6;
        int w = f & 63;
        int gr = r0 + row;
        if (gr >= n) gr = n - 1;
        float4 v = (w < 32)
            ? reinterpret_cast<const float4*>(g_h1)[(size_t)gr * 32 + w]
            : reinterpret_cast<const float4*>(g_h2)[(size_t)gr * 32 + (w - 32)];
        float* dst = hs + row * 257 + w * 4;
        dst[0] = v.x; dst[1] = v.y; dst[2] = v.z; dst[3] = v.w;
    }
    __syncthreads();

    int cg = tid & 7;      // col group: cols cg*5 .. cg*5+4
    int rq = tid >> 3;     // row quad: rows rq*4 .. rq*4+3
    int cbase = cg * 5;

    float acc[4][5];
#pragma unroll
    for (int j = 0; j < 4; j++)
#pragma unroll
        for (int c = 0; c < 5; c++) acc[j][c] = 0.f;

#pragma unroll 4
    for (int k = 0; k < 256; k++) {
        float wv[5];
#pragma unroll
        for (int c = 0; c < 5; c++) wv[c] = ws[k * 40 + cbase + c];
#pragma unroll
        for (int j = 0; j < 4; j++) {
            float h = hs[(rq * 4 + j) * 257 + k];
            acc[j][0] += h * wv[0];
            acc[j][1] += h * wv[1];
            acc[j][2] += h * wv[2];
            acc[j][3] += h * wv[3];
            acc[j][4] += h * wv[4];
        }
    }

#pragma unroll
    for (int j = 0; j < 4; j++) {
        int gr = r0 + rq * 4 + j;
        if (gr < n) {
#pragma unroll
            for (int c = 0; c < 5; c++)
                out[(size_t)gr * 40 + cbase + c] = acc[j][c] + __ldg(b_out + cbase + c);
        }
    }
}

// ---------------------------------------------------------------------------
static void build_csr_and_gather(const int* ei, int E, const float* feat, int n)
{
    int nb_scan = (n + 1023) / 1024;
    zero_deg_kernel<<<256, 256>>>(n);
    count_kernel<<<(E + 255) / 256, 256>>>(ei, E);
    scan1_kernel<<<nb_scan, 1024>>>(n);
    scan2_kernel<<<1, 1024>>>(nb_scan);
    scan3_kernel<<<(n + 255) / 256, 256>>>(n);
    fill_kernel<<<(E + 255) / 256, 256>>>(ei, E);
    gather_kernel<<<(n * 32 + 255) / 256, 256>>>(feat, n);
}

extern "C" void kernel_launch(void* const* d_in, const int* in_sizes, int n_in,
                              void* d_out, int out_size)
{
    const float* x     = (const float*)d_in[0];
    const int*   ei1   = (const int*)d_in[1];
    const int*   ei2   = (const int*)d_in[2];
    const float* wl1   = (const float*)d_in[3];
    const float* wr1   = (const float*)d_in[4];
    const float* b1    = (const float*)d_in[5];
    const float* wl2   = (const float*)d_in[6];
    const float* wr2   = (const float*)d_in[7];
    const float* b2    = (const float*)d_in[8];
    const float* w_out = (const float*)d_in[9];
    const float* b_out = (const float*)d_in[10];

    int n  = in_sizes[0] / D;
    int E1 = in_sizes[1] / 2;
    int E2 = in_sizes[2] / 2;
    int n_rows_out = out_size / 40;

    void *p_h1 = nullptr, *p_h2 = nullptr;
    cudaGetSymbolAddress(&p_h1, g_h1);
    cudaGetSymbolAddress(&p_h2, g_h2);
    float* h1 = (float*)p_h1;
    float* h2 = (float*)p_h2;

    cudaFuncSetAttribute(layer_kernel,
                         cudaFuncAttributeMaxDynamicSharedMemorySize, 196608);
    cudaFuncSetAttribute(out_kernel,
                         cudaFuncAttributeMaxDynamicSharedMemorySize, 172544);

    int layer_blocks = (n + 63) / 64;

    // ---- layer 1 ----
    build_csr_and_gather(ei1, E1, x, n);
    layer_kernel<<<layer_blocks, 256, 196608>>>(x, wl1, wr1, b1, h1, n);

    // ---- layer 2 ----
    build_csr_and_gather(ei2, E2, h1, n);
    layer_kernel<<<layer_blocks, 256, 196608>>>(h1, wl2, wr2, b2, h2, n);

    // ---- JK cat + linear head ----
    out_kernel<<<(n_rows_out + 127) / 128, 256, 172544>>>(
        w_out, b_out, (float*)d_out, n_rows_out);
}